// round 1
// baseline (speedup 1.0000x reference)
#include <cuda_runtime.h>

#define KDIM 128

// Zero-initialized device scratch (re-zeroed by the last block each launch,
// so every graph replay starts from a clean state).
__device__ float g_u[KDIM];
__device__ float g_t[KDIM];
__device__ float g_s[KDIM];
__device__ float g_bias;
__device__ float g_sqsum;
__device__ unsigned int g_count;

__device__ __forceinline__ void process_idx(
    int idx, float val, int n, int m,
    const float* __restrict__ w_bias,
    const float* __restrict__ uV,
    const float* __restrict__ tV,
    const float* __restrict__ bV)
{
    atomicAdd(&g_bias, val * __ldg(&w_bias[idx]));
    if (idx < n) {
        const float4* row = (const float4*)(uV + (size_t)idx * KDIM);
        #pragma unroll
        for (int k = 0; k < KDIM / 4; ++k) {
            float4 r = __ldg(&row[k]);
            atomicAdd(&g_u[4 * k + 0], val * r.x);
            atomicAdd(&g_u[4 * k + 1], val * r.y);
            atomicAdd(&g_u[4 * k + 2], val * r.z);
            atomicAdd(&g_u[4 * k + 3], val * r.w);
        }
    } else if (idx < n + m) {
        const float4* row = (const float4*)(tV + (size_t)(idx - n) * KDIM);
        #pragma unroll
        for (int k = 0; k < KDIM / 4; ++k) {
            float4 r = __ldg(&row[k]);
            atomicAdd(&g_t[4 * k + 0], val * r.x);
            atomicAdd(&g_t[4 * k + 1], val * r.y);
            atomicAdd(&g_t[4 * k + 2], val * r.z);
            atomicAdd(&g_t[4 * k + 3], val * r.w);
        }
    } else {
        const float4* row = (const float4*)(bV + (size_t)(idx - n - m) * KDIM);
        float sq = 0.f;
        #pragma unroll
        for (int k = 0; k < KDIM / 4; ++k) {
            float4 r = __ldg(&row[k]);
            atomicAdd(&g_s[4 * k + 0], val * r.x);
            atomicAdd(&g_s[4 * k + 1], val * r.y);
            atomicAdd(&g_s[4 * k + 2], val * r.z);
            atomicAdd(&g_s[4 * k + 3], val * r.w);
            sq += r.x * r.x + r.y * r.y + r.z * r.z + r.w * r.w;
        }
        atomicAdd(&g_sqsum, val * sq);
    }
}

__global__ void fm_loss_kernel(
    const float* __restrict__ x,
    const float* __restrict__ delta,
    const float* __restrict__ w0,
    const float* __restrict__ w_bias,
    const float* __restrict__ uV,
    const float* __restrict__ tV,
    const float* __restrict__ bV,
    float* __restrict__ out,
    int n, int m)
{
    const int p = n + 2 * m;
    const int p4 = p >> 2;
    const int tid = blockIdx.x * blockDim.x + threadIdx.x;
    const int nthreads = gridDim.x * blockDim.x;

    // Phase 1: sparse scan of x[:p] (vectorized)
    const float4* x4 = (const float4*)x;
    for (int i = tid; i < p4; i += nthreads) {
        float4 v = x4[i];
        if (v.x != 0.f || v.y != 0.f || v.z != 0.f || v.w != 0.f) {
            if (v.x != 0.f) process_idx(4 * i + 0, v.x, n, m, w_bias, uV, tV, bV);
            if (v.y != 0.f) process_idx(4 * i + 1, v.y, n, m, w_bias, uV, tV, bV);
            if (v.z != 0.f) process_idx(4 * i + 2, v.z, n, m, w_bias, uV, tV, bV);
            if (v.w != 0.f) process_idx(4 * i + 3, v.w, n, m, w_bias, uV, tV, bV);
        }
    }
    for (int i = (p4 << 2) + tid; i < p; i += nthreads) {
        float v = x[i];
        if (v != 0.f) process_idx(i, v, n, m, w_bias, uV, tV, bV);
    }

    // Phase 2: last-block-done detection
    __threadfence();
    __syncthreads();
    __shared__ bool s_last;
    if (threadIdx.x == 0)
        s_last = (atomicAdd(&g_count, 1u) == gridDim.x - 1);
    __syncthreads();
    if (!s_last) return;
    __threadfence();  // acquire: make all blocks' scratch writes visible

    // Phase 3: finalize (4 dot products over K=128, warp-shuffle reduce)
    __shared__ float s_part[4][4];
    float ut = 0.f, ts = 0.f, us = 0.f, ss = 0.f;
    if (threadIdx.x < KDIM) {
        float u = g_u[threadIdx.x];
        float t = g_t[threadIdx.x];
        float s = g_s[threadIdx.x];
        ut = u * t; ts = t * s; us = u * s; ss = s * s;
    }
    #pragma unroll
    for (int off = 16; off > 0; off >>= 1) {
        ut += __shfl_down_sync(0xffffffff, ut, off);
        ts += __shfl_down_sync(0xffffffff, ts, off);
        us += __shfl_down_sync(0xffffffff, us, off);
        ss += __shfl_down_sync(0xffffffff, ss, off);
    }
    const int warp = threadIdx.x >> 5;
    const int lane = threadIdx.x & 31;
    if (lane == 0 && warp < 4) {
        s_part[0][warp] = ut;
        s_part[1][warp] = ts;
        s_part[2][warp] = us;
        s_part[3][warp] = ss;
    }
    __syncthreads();
    if (threadIdx.x == 0) {
        float UT = 0.f, TS = 0.f, US = 0.f, SS = 0.f;
        #pragma unroll
        for (int w = 0; w < 4; ++w) {
            UT += s_part[0][w];
            TS += s_part[1][w];
            US += s_part[2][w];
            SS += s_part[3][w];
        }
        float y = w0[0] + g_bias + UT + TS + 0.5f * (SS - g_sqsum) + US;
        float z = y * delta[0];
        // -log_sigmoid(z) = max(-z, 0) + log1p(exp(-|z|))
        out[0] = fmaxf(-z, 0.f) + log1pf(expf(-fabsf(z)));
        // reset scalar scratch for the next replay
        g_bias = 0.f;
        g_sqsum = 0.f;
        g_count = 0u;
    }
    __syncthreads();
    if (threadIdx.x < KDIM) {
        g_u[threadIdx.x] = 0.f;
        g_t[threadIdx.x] = 0.f;
        g_s[threadIdx.x] = 0.f;
    }
}

extern "C" void kernel_launch(void* const* d_in, const int* in_sizes, int n_in,
                              void* d_out, int out_size) {
    const float* x      = (const float*)d_in[0];
    const float* delta  = (const float*)d_in[1];
    // d_in[2] = pmi (unused by the reference)
    const float* w0     = (const float*)d_in[3];
    const float* w_bias = (const float*)d_in[4];
    const float* uV     = (const float*)d_in[5];
    const float* tV     = (const float*)d_in[6];
    const float* bV     = (const float*)d_in[7];
    float* out = (float*)d_out;

    const int n = in_sizes[5] / KDIM;   // u_V is (n, 128)
    const int m = in_sizes[6] / KDIM;   // t_V is (m, 128)
    const int p = n + 2 * m;

    const int threads = 256;
    const int p4 = p >> 2;
    int blocks = (p4 + threads - 1) / threads;
    if (blocks < 1) blocks = 1;

    fm_loss_kernel<<<blocks, threads>>>(x, delta, w0, w_bias, uV, tV, bV, out, n, m);
}